// round 16
// baseline (speedup 1.0000x reference)
#include <cuda_runtime.h>
#include <cstdint>
#include <math.h>

#define TLEN 4096
#define HDIM 256

// ---------------- scratch (static device arrays; no allocation) ----------------
__device__ float g_xsf[TLEN * 1024];   // 16 MB  input-proj forward (reused per layer)
__device__ float g_xsb[TLEN * 1024];   // 16 MB  input-proj backward
__device__ float g_h1 [TLEN * 512];    // 8 MB   layer0 output [hf | hb]
__device__ float g_h2 [TLEN * 512];    // 8 MB   layer1 output
__device__ float g_z  [TLEN * 256];    // 4 MB   fc1 output
__device__ float g_e  [TLEN * 256];    // 4 MB   fc2 output
__device__ float g_nrm[TLEN];          // reciprocal row norms of e

// ---------------- tf32 MMA helpers (fragment layout verified by eet_k) ---------
__device__ __forceinline__ uint32_t f2tf32(float x)
{
    uint32_t r; asm("cvt.rna.tf32.f32 %0, %1;" : "=r"(r) : "f"(x)); return r;
}
__device__ __forceinline__ void mma_tf32(float* d, const uint32_t* a, const uint32_t* b)
{
    asm volatile("mma.sync.aligned.m16n8k8.row.col.f32.tf32.tf32.f32 "
                 "{%0,%1,%2,%3}, {%4,%5,%6,%7}, {%8,%9}, {%0,%1,%2,%3};"
                 : "+f"(d[0]), "+f"(d[1]), "+f"(d[2]), "+f"(d[3])
                 : "r"(a[0]), "r"(a[1]), "r"(a[2]), "r"(a[3]), "r"(b[0]), "r"(b[1]));
}

// ---------------- tf32 GEMM: C = A(MxK) * B(NxK)^T + bias (+relu) --------------
// Block tile 128x128, 8 warps as 4(m) x 2(n), warp tile 32x64,
// mma.m16n8k8 tf32. blockIdx.z selects (B,bias,C) vs (B2,bias2,C2).
__global__ __launch_bounds__(256, 1)
void tgemm_k(const float* __restrict__ A,
             const float* __restrict__ B,  const float* __restrict__ bias,  float* __restrict__ C,
             const float* __restrict__ B2, const float* __restrict__ bias2, float* __restrict__ C2,
             int M, int N, int K, int relu)
{
    __shared__ uint32_t As[16][136];
    __shared__ uint32_t Bs[16][136];

    if (blockIdx.z) { B = B2; bias = bias2; C = C2; }

    const int tid = threadIdx.x;
    const int bm = blockIdx.y << 7;
    const int bn = blockIdx.x << 7;
    const int warp = tid >> 5, lane = tid & 31;
    const int wm = (warp & 3) * 32;
    const int wn = (warp >> 2) * 64;
    const int g = lane >> 2, c = lane & 3;
    const int lr = tid >> 2;
    const int lc = (tid & 3) << 2;

    const float* Ap = A + (size_t)(bm + lr) * K + lc;
    const float* Bp = B + (size_t)(bn + lr) * K + lc;

    float acc[2][8][4];
#pragma unroll
    for (int mt = 0; mt < 2; mt++)
#pragma unroll
        for (int nt = 0; nt < 8; nt++)
#pragma unroll
            for (int i = 0; i < 4; i++) acc[mt][nt][i] = 0.f;

    for (int k0 = 0; k0 < K; k0 += 16) {
        float4 a0 = *(const float4*)(Ap + k0);
        float4 a1 = *(const float4*)(Ap + (size_t)64 * K + k0);
        float4 b0 = *(const float4*)(Bp + k0);
        float4 b1 = *(const float4*)(Bp + (size_t)64 * K + k0);
        __syncthreads();
        As[lc + 0][lr] = f2tf32(a0.x); As[lc + 1][lr] = f2tf32(a0.y);
        As[lc + 2][lr] = f2tf32(a0.z); As[lc + 3][lr] = f2tf32(a0.w);
        As[lc + 0][lr + 64] = f2tf32(a1.x); As[lc + 1][lr + 64] = f2tf32(a1.y);
        As[lc + 2][lr + 64] = f2tf32(a1.z); As[lc + 3][lr + 64] = f2tf32(a1.w);
        Bs[lc + 0][lr] = f2tf32(b0.x); Bs[lc + 1][lr] = f2tf32(b0.y);
        Bs[lc + 2][lr] = f2tf32(b0.z); Bs[lc + 3][lr] = f2tf32(b0.w);
        Bs[lc + 0][lr + 64] = f2tf32(b1.x); Bs[lc + 1][lr + 64] = f2tf32(b1.y);
        Bs[lc + 2][lr + 64] = f2tf32(b1.z); Bs[lc + 3][lr + 64] = f2tf32(b1.w);
        __syncthreads();
#pragma unroll
        for (int kk = 0; kk < 16; kk += 8) {
            uint32_t bf[8][2];
#pragma unroll
            for (int nt = 0; nt < 8; nt++) {
                const int n = wn + nt * 8 + g;
                bf[nt][0] = Bs[kk + c][n];
                bf[nt][1] = Bs[kk + c + 4][n];
            }
#pragma unroll
            for (int mt = 0; mt < 2; mt++) {
                uint32_t af[4];
                const int m = wm + mt * 16 + g;
                af[0] = As[kk + c][m];
                af[1] = As[kk + c][m + 8];
                af[2] = As[kk + c + 4][m];
                af[3] = As[kk + c + 4][m + 8];
#pragma unroll
                for (int nt = 0; nt < 8; nt++)
                    mma_tf32(acc[mt][nt], af, bf[nt]);
            }
        }
    }

    float cb[8][2];
#pragma unroll
    for (int nt = 0; nt < 8; nt++) {
        cb[nt][0] = bias[bn + wn + nt * 8 + 2 * c];
        cb[nt][1] = bias[bn + wn + nt * 8 + 2 * c + 1];
    }
#pragma unroll
    for (int mt = 0; mt < 2; mt++) {
        const int r0 = bm + wm + mt * 16 + g;
        const int r1 = r0 + 8;
#pragma unroll
        for (int nt = 0; nt < 8; nt++) {
            const int col0 = bn + wn + nt * 8 + 2 * c;
            float v00 = acc[mt][nt][0] + cb[nt][0];
            float v01 = acc[mt][nt][1] + cb[nt][1];
            float v10 = acc[mt][nt][2] + cb[nt][0];
            float v11 = acc[mt][nt][3] + cb[nt][1];
            if (relu) {
                v00 = fmaxf(v00, 0.f); v01 = fmaxf(v01, 0.f);
                v10 = fmaxf(v10, 0.f); v11 = fmaxf(v11, 0.f);
            }
            *(float2*)(C + (size_t)r0 * N + col0) = make_float2(v00, v01);
            *(float2*)(C + (size_t)r1 * N + col0) = make_float2(v10, v11);
        }
    }
}

// ---------------- EET: tf32 tensor-core symmetric cosine-distance GEMM ----------
__global__ __launch_bounds__(256, 1)
void eet_k(const float* __restrict__ e, const float* __restrict__ nrm,
           float* __restrict__ out)
{
    __shared__ uint32_t As[16][136];
    __shared__ uint32_t Bs[16][136];

    const int tid = threadIdx.x;
    const int bm = blockIdx.y << 7;
    const int bn = blockIdx.x << 7;
    if (bn < bm) return;               // symmetric: lower-triangle tiles skip

    const int warp = tid >> 5, lane = tid & 31;
    const int wm = (warp & 3) * 32;
    const int wn = (warp >> 2) * 64;
    const int g = lane >> 2, c = lane & 3;

    const int lr = tid >> 2;
    const int lc = (tid & 3) << 2;
    const float* Ap = e + (size_t)(bm + lr) * 256 + lc;
    const float* Bp = e + (size_t)(bn + lr) * 256 + lc;

    float acc[2][8][4];
#pragma unroll
    for (int mt = 0; mt < 2; mt++)
#pragma unroll
        for (int nt = 0; nt < 8; nt++)
#pragma unroll
            for (int i = 0; i < 4; i++) acc[mt][nt][i] = 0.f;

    for (int k0 = 0; k0 < 256; k0 += 16) {
        float4 a0 = *(const float4*)(Ap + k0);
        float4 a1 = *(const float4*)(Ap + (size_t)64 * 256 + k0);
        float4 b0 = *(const float4*)(Bp + k0);
        float4 b1 = *(const float4*)(Bp + (size_t)64 * 256 + k0);
        __syncthreads();
        As[lc + 0][lr] = f2tf32(a0.x); As[lc + 1][lr] = f2tf32(a0.y);
        As[lc + 2][lr] = f2tf32(a0.z); As[lc + 3][lr] = f2tf32(a0.w);
        As[lc + 0][lr + 64] = f2tf32(a1.x); As[lc + 1][lr + 64] = f2tf32(a1.y);
        As[lc + 2][lr + 64] = f2tf32(a1.z); As[lc + 3][lr + 64] = f2tf32(a1.w);
        Bs[lc + 0][lr] = f2tf32(b0.x); Bs[lc + 1][lr] = f2tf32(b0.y);
        Bs[lc + 2][lr] = f2tf32(b0.z); Bs[lc + 3][lr] = f2tf32(b0.w);
        Bs[lc + 0][lr + 64] = f2tf32(b1.x); Bs[lc + 1][lr + 64] = f2tf32(b1.y);
        Bs[lc + 2][lr + 64] = f2tf32(b1.z); Bs[lc + 3][lr + 64] = f2tf32(b1.w);
        __syncthreads();
#pragma unroll
        for (int kk = 0; kk < 16; kk += 8) {
            uint32_t bf[8][2];
#pragma unroll
            for (int nt = 0; nt < 8; nt++) {
                const int n = wn + nt * 8 + g;
                bf[nt][0] = Bs[kk + c][n];
                bf[nt][1] = Bs[kk + c + 4][n];
            }
#pragma unroll
            for (int mt = 0; mt < 2; mt++) {
                uint32_t af[4];
                const int m = wm + mt * 16 + g;
                af[0] = As[kk + c][m];
                af[1] = As[kk + c][m + 8];
                af[2] = As[kk + c + 4][m];
                af[3] = As[kk + c + 4][m + 8];
#pragma unroll
                for (int nt = 0; nt < 8; nt++)
                    mma_tf32(acc[mt][nt], af, bf[nt]);
            }
        }
    }

    float rn[2][2];
#pragma unroll
    for (int mt = 0; mt < 2; mt++) {
        rn[mt][0] = nrm[bm + wm + mt * 16 + g];
        rn[mt][1] = nrm[bm + wm + mt * 16 + g + 8];
    }
    float cn[8][2];
#pragma unroll
    for (int nt = 0; nt < 8; nt++) {
        cn[nt][0] = nrm[bn + wn + nt * 8 + 2 * c];
        cn[nt][1] = nrm[bn + wn + nt * 8 + 2 * c + 1];
    }
#pragma unroll
    for (int mt = 0; mt < 2; mt++) {
        const int r0 = bm + wm + mt * 16 + g;
        const int r1 = r0 + 8;
#pragma unroll
        for (int nt = 0; nt < 8; nt++) {
            const int col0 = bn + wn + nt * 8 + 2 * c;
            const float v00 = 1.f - fmaxf(acc[mt][nt][0] * rn[mt][0] * cn[nt][0], 1e-6f);
            const float v01 = 1.f - fmaxf(acc[mt][nt][1] * rn[mt][0] * cn[nt][1], 1e-6f);
            const float v10 = 1.f - fmaxf(acc[mt][nt][2] * rn[mt][1] * cn[nt][0], 1e-6f);
            const float v11 = 1.f - fmaxf(acc[mt][nt][3] * rn[mt][1] * cn[nt][1], 1e-6f);
            *(float2*)(out + (size_t)r0 * TLEN + col0) = make_float2(v00, v01);
            *(float2*)(out + (size_t)r1 * TLEN + col0) = make_float2(v10, v11);
            if (bn != bm) {
                out[(size_t)col0 * TLEN + r0]       = v00;
                out[(size_t)(col0 + 1) * TLEN + r0] = v01;
                out[(size_t)col0 * TLEN + r1]       = v10;
                out[(size_t)(col0 + 1) * TLEN + r1] = v11;
            }
        }
    }
}

// ---------------- row-norm kernel: stores RECIPROCAL norms ----------------
__global__ void norm_k(const float* __restrict__ e, float* __restrict__ nrm)
{
    const int row  = blockIdx.x * 8 + (threadIdx.x >> 5);
    const int lane = threadIdx.x & 31;
    const float* p = e + (size_t)row * 256;
    float s = 0.f;
#pragma unroll
    for (int i = 0; i < 8; i++) { float v = p[lane + i * 32]; s += v * v; }
#pragma unroll
    for (int o = 16; o; o >>= 1) s += __shfl_xor_sync(0xffffffffu, s, o);
    if (lane == 0) nrm[row] = 1.0f / sqrtf(s);
}

// ---------------- LSTM scan helpers ----------------
#define NCL 16
#define SCAN_THREADS 256

__device__ __forceinline__ uint32_t s2u(const void* p)
{
    uint32_t a;
    asm("{ .reg .u64 t; cvta.to.shared.u64 t, %1; cvt.u32.u64 %0, t; }" : "=r"(a) : "l"(p));
    return a;
}
__device__ __forceinline__ uint32_t mapa_u32(uint32_t la, uint32_t rank)
{
    uint32_t ra;
    asm("mapa.shared::cluster.u32 %0, %1, %2;" : "=r"(ra) : "r"(la), "r"(rank));
    return ra;
}
__device__ __forceinline__ void st_async_f32(uint32_t ra_data, float v, uint32_t ra_bar)
{
    asm volatile("st.async.shared::cluster.mbarrier::complete_tx::bytes.u32 [%0], %1, [%2];"
                 :: "r"(ra_data), "r"(__float_as_uint(v)), "r"(ra_bar) : "memory");
}
__device__ __forceinline__ void mbar_init(uint32_t bar, uint32_t cnt)
{
    asm volatile("mbarrier.init.shared.b64 [%0], %1;" :: "r"(bar), "r"(cnt) : "memory");
}
__device__ __forceinline__ void mbar_expect(uint32_t bar, uint32_t bytes)
{
    asm volatile("mbarrier.arrive.expect_tx.shared.b64 _, [%0], %1;" :: "r"(bar), "r"(bytes) : "memory");
}
__device__ __forceinline__ void mbar_wait(uint32_t bar, uint32_t phase)
{
    asm volatile(
        "{\n\t"
        ".reg .pred P%=;\n\t"
        "W%=:\n\t"
        "mbarrier.try_wait.parity.acquire.cta.shared::cta.b64 P%=, [%0], %1, 0x989680;\n\t"
        "@P%= bra.uni D%=;\n\t"
        "bra.uni W%=;\n\t"
        "D%=:\n\t"
        "}"
        :: "r"(bar), "r"(phase) : "memory");
}
__device__ __forceinline__ float tanha(float x)
{
    float y; asm("tanh.approx.f32 %0, %1;" : "=f"(y) : "f"(x)); return y;
}
__device__ __forceinline__ float sigm(float x)
{
    return fmaf(tanha(0.5f * x), 0.5f, 0.5f);
}
__device__ __forceinline__ void fma2(unsigned long long& acc, unsigned long long a, unsigned long long b)
{
    asm("fma.rn.f32x2 %0, %1, %2, %3;" : "=l"(acc) : "l"(a), "l"(b), "l"(acc));
}

// ---------------- LSTM scan: 2 clusters of 16 CTAs (fwd / bwd) ----------------
// R13/R15 proven design + PRODUCER/CONSUMER BARRIER SPLIT: the in-loop
// __syncthreads is replaced by a named barrier where warps 0-5 only ARRIVE
// (non-blocking, falling through to the next step's mbarrier wait) and the
// gate warps 6-7 SYNC. Ordering safety: producers' next zsh write happens
// only after their mbar_wait for h(s) passes, which transitively requires our
// own gate warps' sends, which follow their zsh reads — so the consumer reads
// always precede the next producer writes, exactly as with __syncthreads.
__global__ void __cluster_dims__(NCL, 1, 1) __launch_bounds__(SCAN_THREADS, 1)
lstm_scan(const float* __restrict__ xsf, const float* __restrict__ xsb,
          const float* __restrict__ whf, const float* __restrict__ whb,
          float* __restrict__ hout)
{
    // padded h layout: 4 segments of 64 floats, stride 68 words -> conflict-free
    __shared__ __align__(16) float hsh[2][4 * 68];
    __shared__ __align__(16) float zsh[SCAN_THREADS];   // partials: [row*4 + q]
    __shared__ __align__(8) unsigned long long mbar[2];

    const int t   = threadIdx.x;
    const int dir = blockIdx.x / NCL;                 // 0 = forward, 1 = backward
    uint32_t rank;
    asm("mov.u32 %0, %%cluster_ctarank;" : "=r"(rank));

    const float* xs  = dir ? xsb : xsf;
    const float* Whh = dir ? whb : whf;

    const int r  = t >> 2;                // gate-row within CTA: 0..63
    const int q  = t & 3;                 // quarter of the dot product
    const int gg = r >> 4;                // gate index 0..3 (i,f,g,o)
    const int uu = r & 15;                // unit within CTA
    const int G  = gg * HDIM + (int)rank * 16 + uu;   // global gate row 0..1023

    // this thread's 64 weights as packed f32x2 pairs (register-resident)
    ulonglong2 wv[8], wv2[8];
    const ulonglong2* wp = reinterpret_cast<const ulonglong2*>(Whh + (size_t)G * HDIM + q * 64);
#pragma unroll
    for (int i = 0; i < 8; i++) wv[i]  = wp[i];
#pragma unroll
    for (int i = 0; i < 8; i++) wv2[i] = wp[8 + i];

    for (int i = t; i < 2 * 4 * 68; i += SCAN_THREADS) ((float*)hsh)[i] = 0.f;

    const uint32_t bar0 = s2u(&mbar[0]);
    if (t == 0) {
        mbar_init(bar0, 1);
        mbar_init(bar0 + 8, 1);
        mbar_expect(bar0, 1024);
        mbar_expect(bar0 + 8, 1024);
    }

    // sender constants (gate warps 6,7): half-warp group grp = (t>>4)&3 owns
    // dest set {grp*4 .. grp*4+3}; lane owns unit (t&15).
    uint32_t rdst[4], rbar[4];
    {
        const int hidx = (int)rank * 16 + (t & 15);
        const int word = (hidx >> 6) * 68 + (hidx & 63);
        const uint32_t la = s2u(&hsh[0][word]);
        const uint32_t pb = (uint32_t)(((t >> 4) & 3) * 4);
#pragma unroll
        for (int k = 0; k < 4; k++) {
            rdst[k] = mapa_u32(la,   pb + k);
            rbar[k] = mapa_u32(bar0, pb + k);
        }
    }

    float creg = 0.f;
    __syncthreads();
    // all CTAs' barriers must be live before any remote st.async
    asm volatile("barrier.cluster.arrive.aligned;" ::: "memory");
    asm volatile("barrier.cluster.wait.aligned;"  ::: "memory");

    // prefetch xs for the first step (q==0 lanes only; folded into partial)
    float xnext = 0.f;
    if (q == 0) {
        const int trow0 = dir ? (TLEN - 1) : 0;
        xnext = xs[(size_t)trow0 * 1024 + G];
    }

    int ph0 = 0, ph1 = 0;
    for (int s = 0; s < TLEN; s++) {
        const int rb = (s + 1) & 1;        // buffer holding h(s-1)
        const int wb = s & 1;              // buffer receiving h(s)
        if (s > 0) {
            if (rb == 0) { mbar_wait(bar0, ph0);     ph0 ^= 1; if (t == 0) mbar_expect(bar0, 1024); }
            else         { mbar_wait(bar0 + 8, ph1); ph1 ^= 1; if (t == 0) mbar_expect(bar0 + 8, 1024); }
        }

        const int trow = dir ? (TLEN - 1 - s) : s;
        const float xcur = xnext;
        if (q == 0 && s + 1 < TLEN) {
            const int tnext = dir ? (TLEN - 2 - s) : (s + 1);
            xnext = xs[(size_t)tnext * 1024 + G];
        }

        // quarter-partial dot: FOUR independent f32x2 chains (dep ~32 cyc)
        const ulonglong2* hp = reinterpret_cast<const ulonglong2*>(&hsh[rb][q * 68]);
        unsigned long long a0 = 0ull, a1 = 0ull, a2 = 0ull, a3 = 0ull;
#pragma unroll
        for (int i = 0; i < 8; i++) {
            ulonglong2 hv = hp[i];
            fma2(a0, wv[i].x, hv.x);
            fma2(a1, wv[i].y, hv.y);
        }
#pragma unroll
        for (int i = 0; i < 8; i++) {
            ulonglong2 hv = hp[8 + i];
            fma2(a2, wv2[i].x, hv.x);
            fma2(a3, wv2[i].y, hv.y);
        }
        float f0, f1, f2, f3, f4, f5, f6, f7;
        asm("mov.b64 {%0, %1}, %2;" : "=f"(f0), "=f"(f1) : "l"(a0));
        asm("mov.b64 {%0, %1}, %2;" : "=f"(f2), "=f"(f3) : "l"(a1));
        asm("mov.b64 {%0, %1}, %2;" : "=f"(f4), "=f"(f5) : "l"(a2));
        asm("mov.b64 {%0, %1}, %2;" : "=f"(f6), "=f"(f7) : "l"(a3));
        zsh[t] = (((f0 + f1) + (f2 + f3)) + ((f4 + f5) + (f6 + f7))) + xcur;

        // producer/consumer split barrier: warps 0-5 arrive (non-blocking),
        // gate warps 6-7 block until all 256 threads have arrived.
        if (t < 192) {
            asm volatile("bar.arrive 1, 256;" ::: "memory");
        } else {
            asm volatile("bar.sync 1, 256;" ::: "memory");

            // gate work: four half-warps, unit (t&15), 4 dests each
            const int u = t & 15;
            const float4 pi = *(const float4*)&zsh[(0 * 16 + u) * 4];
            const float4 pf = *(const float4*)&zsh[(1 * 16 + u) * 4];
            const float4 pg = *(const float4*)&zsh[(2 * 16 + u) * 4];
            const float4 po = *(const float4*)&zsh[(3 * 16 + u) * 4];
            const float zi = (pi.x + pi.y) + (pi.z + pi.w);
            const float zf = (pf.x + pf.y) + (pf.z + pf.w);
            const float zg = (pg.x + pg.y) + (pg.z + pg.w);
            const float zo = (po.x + po.y) + (po.z + po.w);
            const float si = sigm(zi);
            const float sf = sigm(zf);
            const float so = sigm(zo);
            const float c  = sf * creg + si * tanha(zg);
            creg = c;                       // identical across all 4 half-warps
            const float h = so * tanha(c);

            if (s + 1 < TLEN) {
                const uint32_t doff = (uint32_t)wb * 1088u;   // buffer stride 4*68*4 B
                const uint32_t boff = (uint32_t)wb * 8u;
#pragma unroll
                for (int k = 0; k < 4; k++)
                    st_async_f32(rdst[k] + doff, h, rbar[k] + boff);
            }
            if (t >= 224 && t < 240)
                hout[(size_t)trow * 512 + dir * 256 + (int)rank * 16 + u] = h;
        }
    }

    // don't exit while peers may still be consuming our last stores
    asm volatile("barrier.cluster.arrive.aligned;" ::: "memory");
    asm volatile("barrier.cluster.wait.aligned;"  ::: "memory");
}

// ---------------- launcher ----------------
extern "C" void kernel_launch(void* const* d_in, const int* in_sizes, int n_in,
                              void* d_out, int out_size)
{
    (void)in_sizes; (void)n_in; (void)out_size;
    const float* x     = (const float*)d_in[0];
    const float* wih0f = (const float*)d_in[1];
    const float* whh0f = (const float*)d_in[2];
    const float* b0f   = (const float*)d_in[3];
    const float* wih0b = (const float*)d_in[4];
    const float* whh0b = (const float*)d_in[5];
    const float* b0b   = (const float*)d_in[6];
    const float* wih1f = (const float*)d_in[7];
    const float* whh1f = (const float*)d_in[8];
    const float* b1f   = (const float*)d_in[9];
    const float* wih1b = (const float*)d_in[10];
    const float* whh1b = (const float*)d_in[11];
    const float* b1b   = (const float*)d_in[12];
    const float* fc1w  = (const float*)d_in[13];
    const float* fc1b  = (const float*)d_in[14];
    const float* fc2w  = (const float*)d_in[15];
    const float* fc2b  = (const float*)d_in[16];
    float* out = (float*)d_out;

    float *xsf, *xsb, *h1, *h2, *z, *e, *nrm;
    cudaGetSymbolAddress((void**)&xsf, g_xsf);
    cudaGetSymbolAddress((void**)&xsb, g_xsb);
    cudaGetSymbolAddress((void**)&h1,  g_h1);
    cudaGetSymbolAddress((void**)&h2,  g_h2);
    cudaGetSymbolAddress((void**)&z,   g_z);
    cudaGetSymbolAddress((void**)&e,   g_e);
    cudaGetSymbolAddress((void**)&nrm, g_nrm);

    // opt in to 16-CTA (non-portable) cluster size
    static int attr_done = 0;
    if (!attr_done) {
        cudaFuncSetAttribute(lstm_scan, cudaFuncAttributeNonPortableClusterSizeAllowed, 1);
        attr_done = 1;
    }

    const dim3 blk(256);

    // layer 0: both direction input projections, tf32 MMA, one launch
    tgemm_k<<<dim3(8, 32, 2), blk>>>(x, wih0f, b0f, xsf, wih0b, b0b, xsb,
                                     TLEN, 1024, 128, 0);
    // layer 0 scan
    lstm_scan<<<2 * NCL, SCAN_THREADS>>>(xsf, xsb, whh0f, whh0b, h1);
    // layer 1: both direction input projections (K=512), tf32 MMA
    tgemm_k<<<dim3(8, 32, 2), blk>>>(h1, wih1f, b1f, xsf, wih1b, b1b, xsb,
                                     TLEN, 1024, 512, 0);
    // layer 1 scan
    lstm_scan<<<2 * NCL, SCAN_THREADS>>>(xsf, xsb, whh1f, whh1b, h2);
    // fc1 (relu), fc2 — tf32 MMA
    tgemm_k<<<dim3(2, 32, 1), blk>>>(h2, fc1w, fc1b, z, fc1w, fc1b, z,
                                     TLEN, 256, 512, 1);
    tgemm_k<<<dim3(2, 32, 1), blk>>>(z, fc2w, fc2b, e, fc2w, fc2b, e,
                                     TLEN, 256, 256, 0);
    // reciprocal norms + symmetric tf32 tensor-core cosine-distance matrix
    norm_k<<<TLEN / 8, 256>>>(e, nrm);
    eet_k<<<dim3(32, 32), blk>>>(e, nrm, out);
}

// round 17
// speedup vs baseline: 1.0247x; 1.0247x over previous
#include <cuda_runtime.h>
#include <cstdint>
#include <math.h>

#define TLEN 4096
#define HDIM 256

// ---------------- scratch (static device arrays; no allocation) ----------------
__device__ float g_xsf[TLEN * 1024];   // 16 MB  input-proj forward (reused per layer)
__device__ float g_xsb[TLEN * 1024];   // 16 MB  input-proj backward
__device__ float g_h1 [TLEN * 512];    // 8 MB   layer0 output [hf | hb]
__device__ float g_h2 [TLEN * 512];    // 8 MB   layer1 output
__device__ float g_z  [TLEN * 256];    // 4 MB   fc1 output
__device__ float g_e  [TLEN * 256];    // 4 MB   fc2 output
__device__ float g_nrm[TLEN];          // reciprocal row norms of e

// ---------------- tf32 MMA helpers (fragment layout verified by eet_k) ---------
__device__ __forceinline__ uint32_t f2tf32(float x)
{
    uint32_t r; asm("cvt.rna.tf32.f32 %0, %1;" : "=r"(r) : "f"(x)); return r;
}
__device__ __forceinline__ void mma_tf32(float* d, const uint32_t* a, const uint32_t* b)
{
    asm volatile("mma.sync.aligned.m16n8k8.row.col.f32.tf32.tf32.f32 "
                 "{%0,%1,%2,%3}, {%4,%5,%6,%7}, {%8,%9}, {%0,%1,%2,%3};"
                 : "+f"(d[0]), "+f"(d[1]), "+f"(d[2]), "+f"(d[3])
                 : "r"(a[0]), "r"(a[1]), "r"(a[2]), "r"(a[3]), "r"(b[0]), "r"(b[1]));
}

// ---------------- tf32 GEMM: C = A(MxK) * B(NxK)^T + bias (+relu) --------------
// Block tile 128x128, 8 warps as 4(m) x 2(n), warp tile 32x64,
// mma.m16n8k8 tf32. blockIdx.z selects (B,bias,C) vs (B2,bias2,C2).
// Occupancy 2: second resident CTA hides the smem staging / sync phases.
__global__ __launch_bounds__(256, 2)
void tgemm_k(const float* __restrict__ A,
             const float* __restrict__ B,  const float* __restrict__ bias,  float* __restrict__ C,
             const float* __restrict__ B2, const float* __restrict__ bias2, float* __restrict__ C2,
             int M, int N, int K, int relu)
{
    __shared__ uint32_t As[16][136];
    __shared__ uint32_t Bs[16][136];

    if (blockIdx.z) { B = B2; bias = bias2; C = C2; }

    const int tid = threadIdx.x;
    const int bm = blockIdx.y << 7;
    const int bn = blockIdx.x << 7;
    const int warp = tid >> 5, lane = tid & 31;
    const int wm = (warp & 3) * 32;
    const int wn = (warp >> 2) * 64;
    const int g = lane >> 2, c = lane & 3;
    const int lr = tid >> 2;
    const int lc = (tid & 3) << 2;

    const float* Ap = A + (size_t)(bm + lr) * K + lc;
    const float* Bp = B + (size_t)(bn + lr) * K + lc;

    float acc[2][8][4];
#pragma unroll
    for (int mt = 0; mt < 2; mt++)
#pragma unroll
        for (int nt = 0; nt < 8; nt++)
#pragma unroll
            for (int i = 0; i < 4; i++) acc[mt][nt][i] = 0.f;

    for (int k0 = 0; k0 < K; k0 += 16) {
        float4 a0 = *(const float4*)(Ap + k0);
        float4 a1 = *(const float4*)(Ap + (size_t)64 * K + k0);
        float4 b0 = *(const float4*)(Bp + k0);
        float4 b1 = *(const float4*)(Bp + (size_t)64 * K + k0);
        __syncthreads();
        As[lc + 0][lr] = f2tf32(a0.x); As[lc + 1][lr] = f2tf32(a0.y);
        As[lc + 2][lr] = f2tf32(a0.z); As[lc + 3][lr] = f2tf32(a0.w);
        As[lc + 0][lr + 64] = f2tf32(a1.x); As[lc + 1][lr + 64] = f2tf32(a1.y);
        As[lc + 2][lr + 64] = f2tf32(a1.z); As[lc + 3][lr + 64] = f2tf32(a1.w);
        Bs[lc + 0][lr] = f2tf32(b0.x); Bs[lc + 1][lr] = f2tf32(b0.y);
        Bs[lc + 2][lr] = f2tf32(b0.z); Bs[lc + 3][lr] = f2tf32(b0.w);
        Bs[lc + 0][lr + 64] = f2tf32(b1.x); Bs[lc + 1][lr + 64] = f2tf32(b1.y);
        Bs[lc + 2][lr + 64] = f2tf32(b1.z); Bs[lc + 3][lr + 64] = f2tf32(b1.w);
        __syncthreads();
#pragma unroll
        for (int kk = 0; kk < 16; kk += 8) {
            uint32_t bf[8][2];
#pragma unroll
            for (int nt = 0; nt < 8; nt++) {
                const int n = wn + nt * 8 + g;
                bf[nt][0] = Bs[kk + c][n];
                bf[nt][1] = Bs[kk + c + 4][n];
            }
#pragma unroll
            for (int mt = 0; mt < 2; mt++) {
                uint32_t af[4];
                const int m = wm + mt * 16 + g;
                af[0] = As[kk + c][m];
                af[1] = As[kk + c][m + 8];
                af[2] = As[kk + c + 4][m];
                af[3] = As[kk + c + 4][m + 8];
#pragma unroll
                for (int nt = 0; nt < 8; nt++)
                    mma_tf32(acc[mt][nt], af, bf[nt]);
            }
        }
    }

    float cb[8][2];
#pragma unroll
    for (int nt = 0; nt < 8; nt++) {
        cb[nt][0] = bias[bn + wn + nt * 8 + 2 * c];
        cb[nt][1] = bias[bn + wn + nt * 8 + 2 * c + 1];
    }
#pragma unroll
    for (int mt = 0; mt < 2; mt++) {
        const int r0 = bm + wm + mt * 16 + g;
        const int r1 = r0 + 8;
#pragma unroll
        for (int nt = 0; nt < 8; nt++) {
            const int col0 = bn + wn + nt * 8 + 2 * c;
            float v00 = acc[mt][nt][0] + cb[nt][0];
            float v01 = acc[mt][nt][1] + cb[nt][1];
            float v10 = acc[mt][nt][2] + cb[nt][0];
            float v11 = acc[mt][nt][3] + cb[nt][1];
            if (relu) {
                v00 = fmaxf(v00, 0.f); v01 = fmaxf(v01, 0.f);
                v10 = fmaxf(v10, 0.f); v11 = fmaxf(v11, 0.f);
            }
            *(float2*)(C + (size_t)r0 * N + col0) = make_float2(v00, v01);
            *(float2*)(C + (size_t)r1 * N + col0) = make_float2(v10, v11);
        }
    }
}

// ---------------- EET: tf32 tensor-core symmetric cosine-distance GEMM ----------
__global__ __launch_bounds__(256, 2)
void eet_k(const float* __restrict__ e, const float* __restrict__ nrm,
           float* __restrict__ out)
{
    __shared__ uint32_t As[16][136];
    __shared__ uint32_t Bs[16][136];

    const int tid = threadIdx.x;
    const int bm = blockIdx.y << 7;
    const int bn = blockIdx.x << 7;
    if (bn < bm) return;               // symmetric: lower-triangle tiles skip

    const int warp = tid >> 5, lane = tid & 31;
    const int wm = (warp & 3) * 32;
    const int wn = (warp >> 2) * 64;
    const int g = lane >> 2, c = lane & 3;

    const int lr = tid >> 2;
    const int lc = (tid & 3) << 2;
    const float* Ap = e + (size_t)(bm + lr) * 256 + lc;
    const float* Bp = e + (size_t)(bn + lr) * 256 + lc;

    float acc[2][8][4];
#pragma unroll
    for (int mt = 0; mt < 2; mt++)
#pragma unroll
        for (int nt = 0; nt < 8; nt++)
#pragma unroll
            for (int i = 0; i < 4; i++) acc[mt][nt][i] = 0.f;

    for (int k0 = 0; k0 < 256; k0 += 16) {
        float4 a0 = *(const float4*)(Ap + k0);
        float4 a1 = *(const float4*)(Ap + (size_t)64 * 256 + k0);
        float4 b0 = *(const float4*)(Bp + k0);
        float4 b1 = *(const float4*)(Bp + (size_t)64 * 256 + k0);
        __syncthreads();
        As[lc + 0][lr] = f2tf32(a0.x); As[lc + 1][lr] = f2tf32(a0.y);
        As[lc + 2][lr] = f2tf32(a0.z); As[lc + 3][lr] = f2tf32(a0.w);
        As[lc + 0][lr + 64] = f2tf32(a1.x); As[lc + 1][lr + 64] = f2tf32(a1.y);
        As[lc + 2][lr + 64] = f2tf32(a1.z); As[lc + 3][lr + 64] = f2tf32(a1.w);
        Bs[lc + 0][lr] = f2tf32(b0.x); Bs[lc + 1][lr] = f2tf32(b0.y);
        Bs[lc + 2][lr] = f2tf32(b0.z); Bs[lc + 3][lr] = f2tf32(b0.w);
        Bs[lc + 0][lr + 64] = f2tf32(b1.x); Bs[lc + 1][lr + 64] = f2tf32(b1.y);
        Bs[lc + 2][lr + 64] = f2tf32(b1.z); Bs[lc + 3][lr + 64] = f2tf32(b1.w);
        __syncthreads();
#pragma unroll
        for (int kk = 0; kk < 16; kk += 8) {
            uint32_t bf[8][2];
#pragma unroll
            for (int nt = 0; nt < 8; nt++) {
                const int n = wn + nt * 8 + g;
                bf[nt][0] = Bs[kk + c][n];
                bf[nt][1] = Bs[kk + c + 4][n];
            }
#pragma unroll
            for (int mt = 0; mt < 2; mt++) {
                uint32_t af[4];
                const int m = wm + mt * 16 + g;
                af[0] = As[kk + c][m];
                af[1] = As[kk + c][m + 8];
                af[2] = As[kk + c + 4][m];
                af[3] = As[kk + c + 4][m + 8];
#pragma unroll
                for (int nt = 0; nt < 8; nt++)
                    mma_tf32(acc[mt][nt], af, bf[nt]);
            }
        }
    }

    float rn[2][2];
#pragma unroll
    for (int mt = 0; mt < 2; mt++) {
        rn[mt][0] = nrm[bm + wm + mt * 16 + g];
        rn[mt][1] = nrm[bm + wm + mt * 16 + g + 8];
    }
    float cn[8][2];
#pragma unroll
    for (int nt = 0; nt < 8; nt++) {
        cn[nt][0] = nrm[bn + wn + nt * 8 + 2 * c];
        cn[nt][1] = nrm[bn + wn + nt * 8 + 2 * c + 1];
    }
#pragma unroll
    for (int mt = 0; mt < 2; mt++) {
        const int r0 = bm + wm + mt * 16 + g;
        const int r1 = r0 + 8;
#pragma unroll
        for (int nt = 0; nt < 8; nt++) {
            const int col0 = bn + wn + nt * 8 + 2 * c;
            const float v00 = 1.f - fmaxf(acc[mt][nt][0] * rn[mt][0] * cn[nt][0], 1e-6f);
            const float v01 = 1.f - fmaxf(acc[mt][nt][1] * rn[mt][0] * cn[nt][1], 1e-6f);
            const float v10 = 1.f - fmaxf(acc[mt][nt][2] * rn[mt][1] * cn[nt][0], 1e-6f);
            const float v11 = 1.f - fmaxf(acc[mt][nt][3] * rn[mt][1] * cn[nt][1], 1e-6f);
            *(float2*)(out + (size_t)r0 * TLEN + col0) = make_float2(v00, v01);
            *(float2*)(out + (size_t)r1 * TLEN + col0) = make_float2(v10, v11);
            if (bn != bm) {
                out[(size_t)col0 * TLEN + r0]       = v00;
                out[(size_t)(col0 + 1) * TLEN + r0] = v01;
                out[(size_t)col0 * TLEN + r1]       = v10;
                out[(size_t)(col0 + 1) * TLEN + r1] = v11;
            }
        }
    }
}

// ---------------- row-norm kernel: stores RECIPROCAL norms ----------------
__global__ void norm_k(const float* __restrict__ e, float* __restrict__ nrm)
{
    const int row  = blockIdx.x * 8 + (threadIdx.x >> 5);
    const int lane = threadIdx.x & 31;
    const float* p = e + (size_t)row * 256;
    float s = 0.f;
#pragma unroll
    for (int i = 0; i < 8; i++) { float v = p[lane + i * 32]; s += v * v; }
#pragma unroll
    for (int o = 16; o; o >>= 1) s += __shfl_xor_sync(0xffffffffu, s, o);
    if (lane == 0) nrm[row] = 1.0f / sqrtf(s);
}

// ---------------- LSTM scan helpers ----------------
#define NCL 16
#define SCAN_THREADS 256

__device__ __forceinline__ uint32_t s2u(const void* p)
{
    uint32_t a;
    asm("{ .reg .u64 t; cvta.to.shared.u64 t, %1; cvt.u32.u64 %0, t; }" : "=r"(a) : "l"(p));
    return a;
}
__device__ __forceinline__ uint32_t mapa_u32(uint32_t la, uint32_t rank)
{
    uint32_t ra;
    asm("mapa.shared::cluster.u32 %0, %1, %2;" : "=r"(ra) : "r"(la), "r"(rank));
    return ra;
}
__device__ __forceinline__ void st_async_f32(uint32_t ra_data, float v, uint32_t ra_bar)
{
    asm volatile("st.async.shared::cluster.mbarrier::complete_tx::bytes.u32 [%0], %1, [%2];"
                 :: "r"(ra_data), "r"(__float_as_uint(v)), "r"(ra_bar) : "memory");
}
__device__ __forceinline__ void mbar_init(uint32_t bar, uint32_t cnt)
{
    asm volatile("mbarrier.init.shared.b64 [%0], %1;" :: "r"(bar), "r"(cnt) : "memory");
}
__device__ __forceinline__ void mbar_expect(uint32_t bar, uint32_t bytes)
{
    asm volatile("mbarrier.arrive.expect_tx.shared.b64 _, [%0], %1;" :: "r"(bar), "r"(bytes) : "memory");
}
__device__ __forceinline__ void mbar_wait(uint32_t bar, uint32_t phase)
{
    asm volatile(
        "{\n\t"
        ".reg .pred P%=;\n\t"
        "W%=:\n\t"
        "mbarrier.try_wait.parity.acquire.cta.shared::cta.b64 P%=, [%0], %1, 0x989680;\n\t"
        "@P%= bra.uni D%=;\n\t"
        "bra.uni W%=;\n\t"
        "D%=:\n\t"
        "}"
        :: "r"(bar), "r"(phase) : "memory");
}
__device__ __forceinline__ float tanha(float x)
{
    float y; asm("tanh.approx.f32 %0, %1;" : "=f"(y) : "f"(x)); return y;
}
__device__ __forceinline__ float sigm(float x)
{
    return fmaf(tanha(0.5f * x), 0.5f, 0.5f);
}
__device__ __forceinline__ void fma2(unsigned long long& acc, unsigned long long a, unsigned long long b)
{
    asm("fma.rn.f32x2 %0, %1, %2, %3;" : "=l"(acc) : "l"(a), "l"(b), "l"(acc));
}

// ---------------- LSTM scan: 2 clusters of 16 CTAs (fwd / bwd) ----------------
// R13/R15 proven design (EXACT revert of the R16 barrier split): 16 units per
// CTA, warps 6+7 as four redundant gate half-warps with 4 dests each; matvec
// in four independent f32x2 chains; plain __syncthreads handoff.
__global__ void __cluster_dims__(NCL, 1, 1) __launch_bounds__(SCAN_THREADS, 1)
lstm_scan(const float* __restrict__ xsf, const float* __restrict__ xsb,
          const float* __restrict__ whf, const float* __restrict__ whb,
          float* __restrict__ hout)
{
    // padded h layout: 4 segments of 64 floats, stride 68 words -> conflict-free
    __shared__ __align__(16) float hsh[2][4 * 68];
    __shared__ __align__(16) float zsh[SCAN_THREADS];   // partials: [row*4 + q]
    __shared__ __align__(8) unsigned long long mbar[2];

    const int t   = threadIdx.x;
    const int dir = blockIdx.x / NCL;                 // 0 = forward, 1 = backward
    uint32_t rank;
    asm("mov.u32 %0, %%cluster_ctarank;" : "=r"(rank));

    const float* xs  = dir ? xsb : xsf;
    const float* Whh = dir ? whb : whf;

    const int r  = t >> 2;                // gate-row within CTA: 0..63
    const int q  = t & 3;                 // quarter of the dot product
    const int gg = r >> 4;                // gate index 0..3 (i,f,g,o)
    const int uu = r & 15;                // unit within CTA
    const int G  = gg * HDIM + (int)rank * 16 + uu;   // global gate row 0..1023

    // this thread's 64 weights as packed f32x2 pairs (register-resident)
    ulonglong2 wv[8], wv2[8];
    const ulonglong2* wp = reinterpret_cast<const ulonglong2*>(Whh + (size_t)G * HDIM + q * 64);
#pragma unroll
    for (int i = 0; i < 8; i++) wv[i]  = wp[i];
#pragma unroll
    for (int i = 0; i < 8; i++) wv2[i] = wp[8 + i];

    for (int i = t; i < 2 * 4 * 68; i += SCAN_THREADS) ((float*)hsh)[i] = 0.f;

    const uint32_t bar0 = s2u(&mbar[0]);
    if (t == 0) {
        mbar_init(bar0, 1);
        mbar_init(bar0 + 8, 1);
        mbar_expect(bar0, 1024);
        mbar_expect(bar0 + 8, 1024);
    }

    // sender constants (gate warps 6,7): half-warp group grp = (t>>4)&3 owns
    // dest set {grp*4 .. grp*4+3}; lane owns unit (t&15).
    uint32_t rdst[4], rbar[4];
    {
        const int hidx = (int)rank * 16 + (t & 15);
        const int word = (hidx >> 6) * 68 + (hidx & 63);
        const uint32_t la = s2u(&hsh[0][word]);
        const uint32_t pb = (uint32_t)(((t >> 4) & 3) * 4);
#pragma unroll
        for (int k = 0; k < 4; k++) {
            rdst[k] = mapa_u32(la,   pb + k);
            rbar[k] = mapa_u32(bar0, pb + k);
        }
    }

    float creg = 0.f;
    __syncthreads();
    // all CTAs' barriers must be live before any remote st.async
    asm volatile("barrier.cluster.arrive.aligned;" ::: "memory");
    asm volatile("barrier.cluster.wait.aligned;"  ::: "memory");

    // prefetch xs for the first step (q==0 lanes only; folded into partial)
    float xnext = 0.f;
    if (q == 0) {
        const int trow0 = dir ? (TLEN - 1) : 0;
        xnext = xs[(size_t)trow0 * 1024 + G];
    }

    int ph0 = 0, ph1 = 0;
    for (int s = 0; s < TLEN; s++) {
        const int rb = (s + 1) & 1;        // buffer holding h(s-1)
        const int wb = s & 1;              // buffer receiving h(s)
        if (s > 0) {
            if (rb == 0) { mbar_wait(bar0, ph0);     ph0 ^= 1; if (t == 0) mbar_expect(bar0, 1024); }
            else         { mbar_wait(bar0 + 8, ph1); ph1 ^= 1; if (t == 0) mbar_expect(bar0 + 8, 1024); }
        }

        const int trow = dir ? (TLEN - 1 - s) : s;
        const float xcur = xnext;
        if (q == 0 && s + 1 < TLEN) {
            const int tnext = dir ? (TLEN - 2 - s) : (s + 1);
            xnext = xs[(size_t)tnext * 1024 + G];
        }

        // quarter-partial dot: FOUR independent f32x2 chains (dep ~32 cyc)
        const ulonglong2* hp = reinterpret_cast<const ulonglong2*>(&hsh[rb][q * 68]);
        unsigned long long a0 = 0ull, a1 = 0ull, a2 = 0ull, a3 = 0ull;
#pragma unroll
        for (int i = 0; i < 8; i++) {
            ulonglong2 hv = hp[i];
            fma2(a0, wv[i].x, hv.x);
            fma2(a1, wv[i].y, hv.y);
        }
#pragma unroll
        for (int i = 0; i < 8; i++) {
            ulonglong2 hv = hp[8 + i];
            fma2(a2, wv2[i].x, hv.x);
            fma2(a3, wv2[i].y, hv.y);
        }
        float f0, f1, f2, f3, f4, f5, f6, f7;
        asm("mov.b64 {%0, %1}, %2;" : "=f"(f0), "=f"(f1) : "l"(a0));
        asm("mov.b64 {%0, %1}, %2;" : "=f"(f2), "=f"(f3) : "l"(a1));
        asm("mov.b64 {%0, %1}, %2;" : "=f"(f4), "=f"(f5) : "l"(a2));
        asm("mov.b64 {%0, %1}, %2;" : "=f"(f6), "=f"(f7) : "l"(a3));
        zsh[t] = (((f0 + f1) + (f2 + f3)) + ((f4 + f5) + (f6 + f7))) + xcur;
        __syncthreads();   // all partials visible; all reads of buffer rb done

        if (t >= 192) {    // warps 6+7: four half-warps, unit (t&15), 4 dests each
            const int u = t & 15;
            const float4 pi = *(const float4*)&zsh[(0 * 16 + u) * 4];
            const float4 pf = *(const float4*)&zsh[(1 * 16 + u) * 4];
            const float4 pg = *(const float4*)&zsh[(2 * 16 + u) * 4];
            const float4 po = *(const float4*)&zsh[(3 * 16 + u) * 4];
            const float zi = (pi.x + pi.y) + (pi.z + pi.w);
            const float zf = (pf.x + pf.y) + (pf.z + pf.w);
            const float zg = (pg.x + pg.y) + (pg.z + pg.w);
            const float zo = (po.x + po.y) + (po.z + po.w);
            const float si = sigm(zi);
            const float sf = sigm(zf);
            const float so = sigm(zo);
            const float c  = sf * creg + si * tanha(zg);
            creg = c;                       // identical across all 4 half-warps
            const float h = so * tanha(c);

            if (s + 1 < TLEN) {
                const uint32_t doff = (uint32_t)wb * 1088u;   // buffer stride 4*68*4 B
                const uint32_t boff = (uint32_t)wb * 8u;
#pragma unroll
                for (int k = 0; k < 4; k++)
                    st_async_f32(rdst[k] + doff, h, rbar[k] + boff);
            }
            if (t >= 224 && t < 240)
                hout[(size_t)trow * 512 + dir * 256 + (int)rank * 16 + u] = h;
        }
    }

    // don't exit while peers may still be consuming our last stores
    asm volatile("barrier.cluster.arrive.aligned;" ::: "memory");
    asm volatile("barrier.cluster.wait.aligned;"  ::: "memory");
}

// ---------------- launcher ----------------
extern "C" void kernel_launch(void* const* d_in, const int* in_sizes, int n_in,
                              void* d_out, int out_size)
{
    (void)in_sizes; (void)n_in; (void)out_size;
    const float* x     = (const float*)d_in[0];
    const float* wih0f = (const float*)d_in[1];
    const float* whh0f = (const float*)d_in[2];
    const float* b0f   = (const float*)d_in[3];
    const float* wih0b = (const float*)d_in[4];
    const float* whh0b = (const float*)d_in[5];
    const float* b0b   = (const float*)d_in[6];
    const float* wih1f = (const float*)d_in[7];
    const float* whh1f = (const float*)d_in[8];
    const float* b1f   = (const float*)d_in[9];
    const float* wih1b = (const float*)d_in[10];
    const float* whh1b = (const float*)d_in[11];
    const float* b1b   = (const float*)d_in[12];
    const float* fc1w  = (const float*)d_in[13];
    const float* fc1b  = (const float*)d_in[14];
    const float* fc2w  = (const float*)d_in[15];
    const float* fc2b  = (const float*)d_in[16];
    float* out = (float*)d_out;

    float *xsf, *xsb, *h1, *h2, *z, *e, *nrm;
    cudaGetSymbolAddress((void**)&xsf, g_xsf);
    cudaGetSymbolAddress((void**)&xsb, g_xsb);
    cudaGetSymbolAddress((void**)&h1,  g_h1);
    cudaGetSymbolAddress((void**)&h2,  g_h2);
    cudaGetSymbolAddress((void**)&z,   g_z);
    cudaGetSymbolAddress((void**)&e,   g_e);
    cudaGetSymbolAddress((void**)&nrm, g_nrm);

    // opt in to 16-CTA (non-portable) cluster size
    static int attr_done = 0;
    if (!attr_done) {
        cudaFuncSetAttribute(lstm_scan, cudaFuncAttributeNonPortableClusterSizeAllowed, 1);
        attr_done = 1;
    }

    const dim3 blk(256);

    // layer 0: both direction input projections, tf32 MMA, one launch
    tgemm_k<<<dim3(8, 32, 2), blk>>>(x, wih0f, b0f, xsf, wih0b, b0b, xsb,
                                     TLEN, 1024, 128, 0);
    // layer 0 scan
    lstm_scan<<<2 * NCL, SCAN_THREADS>>>(xsf, xsb, whh0f, whh0b, h1);
    // layer 1: both direction input projections (K=512), tf32 MMA
    tgemm_k<<<dim3(8, 32, 2), blk>>>(h1, wih1f, b1f, xsf, wih1b, b1b, xsb,
                                     TLEN, 1024, 512, 0);
    // layer 1 scan
    lstm_scan<<<2 * NCL, SCAN_THREADS>>>(xsf, xsb, whh1f, whh1b, h2);
    // fc1 (relu), fc2 — tf32 MMA
    tgemm_k<<<dim3(2, 32, 1), blk>>>(h2, fc1w, fc1b, z, fc1w, fc1b, z,
                                     TLEN, 256, 512, 1);
    tgemm_k<<<dim3(2, 32, 1), blk>>>(z, fc2w, fc2b, e, fc2w, fc2b, e,
                                     TLEN, 256, 256, 0);
    // reciprocal norms + symmetric tf32 tensor-core cosine-distance matrix
    norm_k<<<TLEN / 8, 256>>>(e, nrm);
    eet_k<<<dim3(32, 32), blk>>>(e, nrm, out);
}